// round 17
// baseline (speedup 1.0000x reference)
#include <cuda_runtime.h>
#include <cuda_fp16.h>
#include <mma.h>
#include <cstdint>

using namespace nvcuda;

// Shape: B=16, n=4096, D=1024. Tokens = 65536.
#define B_SZ   16
#define N_TOK  4096
#define D_DIM  1024
#define NTOK_TOTAL (B_SZ * N_TOK)

#define NCHUNKS 4          // 1024 / BN
#define BM 128
#define BN 256
#define BK 16
#define KSTEPS (D_DIM / BK)   // 64

#define XPAD 24            // fp16 per x-row in smem (16 + 8 pad) = 48 B
#define WPAD 264           // fp16 per w-row in smem (256 + 8 pad) = 528 B
#define EPAD 260           // f32 per epilogue row

// Scratch (__device__ globals: allocation-free rule)
__device__ float g_part[NCHUNKS][NTOK_TOTAL];
__device__ __half g_xf[(size_t)NTOK_TOTAL * D_DIM];    // fp16(x)
__device__ __half g_Wh[D_DIM * D_DIM];                 // fp16(W1) [k][e]

// smem layout (bytes)
#define ST_XH 0                      // 128 * 48 = 6144
#define ST_WH 6144                   // 16 * 528 = 8448
#define STAGE_B 14592
#define NSLOT 8                      // 8 slots = 116736
#define EP_BYTES (BM * EPAD * 4)     // 133120 (> 8*STAGE_B) -> epilogue aliases slots
#define SM_B1 EP_BYTES               // 133120, 256 f32
#define SM_W2 (SM_B1 + 1024)
#define SMEM_TOTAL (SM_W2 + 1024)    // 135168

__device__ __forceinline__ uint32_t smem_u32(const void* p) {
    uint32_t a;
    asm("{ .reg .u64 t; cvta.to.shared.u64 t, %1; cvt.u32.u64 %0, t; }" : "=r"(a) : "l"(p));
    return a;
}
#define CP16(dst, src) \
    asm volatile("cp.async.cg.shared.global [%0], [%1], 16;" :: "r"(dst), "l"(src) : "memory")
#define CP_COMMIT() asm volatile("cp.async.commit_group;" ::: "memory")
#define CP_WAIT(n)  asm volatile("cp.async.wait_group %0;" :: "n"(n) : "memory")

// ---------------------------------------------------------------------------
// Prep: x -> fp16, W1 -> fp16.
// ---------------------------------------------------------------------------
__global__ __launch_bounds__(256)
void prep_x_kernel(const float* __restrict__ x)
{
    const size_t i4 = (size_t)blockIdx.x * 256 + threadIdx.x;   // float4 index
    float4 v = ((const float4*)x)[i4];
    ((__half2*)g_xf)[i4 * 2]     = __floats2half2_rn(v.x, v.y);
    ((__half2*)g_xf)[i4 * 2 + 1] = __floats2half2_rn(v.z, v.w);
}

__global__ __launch_bounds__(256)
void prep_w_kernel(const float* __restrict__ W1)
{
    const size_t i4 = (size_t)blockIdx.x * 256 + threadIdx.x;
    float4 v = ((const float4*)W1)[i4];
    ((__half2*)g_Wh)[i4 * 2]     = __floats2half2_rn(v.x, v.y);
    ((__half2*)g_Wh)[i4 * 2 + 1] = __floats2half2_rn(v.z, v.w);
}

// ---------------------------------------------------------------------------
// Kernel A: fp16 wmma logits GEMM, deep cp.async pipeline.
// Grid (4, 512): x = n-chunk (256 feats), y = m-tile (128 tokens).
// 8 warps, warp tile 64x64 (2m x 4n). K in 64 stages of BK=16,
// 8 smem slots, prefetch depth 7, two barriers per stage (proven ordering).
// ---------------------------------------------------------------------------
__global__ __launch_bounds__(256, 1)
void logits_wmma_kernel(const float* __restrict__ b1,
                        const float* __restrict__ W2)
{
    extern __shared__ char smem[];
    const uint32_t sb = smem_u32(smem);
    const int tid = threadIdx.x;
    const int wid = tid >> 5;
    const int n0  = blockIdx.x * BN;
    const int m0  = blockIdx.y * BM;

    float* s_b1 = (float*)(smem + SM_B1);
    float* s_w2 = (float*)(smem + SM_W2);
    if (tid < 256) { s_b1[tid] = b1[n0 + tid]; s_w2[tid] = W2[n0 + tid]; }

    // per-thread cp.async assignments
    // x: 128 rows x 16 fp16 = 32B/row = 2x16B chunks; 256 chunks, 1/thread
    const int xrow = tid >> 1;                  // 0..127
    const int xcc  = tid & 1;                   // chunk in row
    const size_t xg0 = (size_t)(m0 + xrow) * D_DIM + xcc * 8;
    const uint32_t xs0 = xrow * (XPAD * 2) + xcc * 16;

    auto issue_stage = [&](int kt) {
        const int k0 = kt * BK;
        const uint32_t s = sb + (kt & 7) * STAGE_B;
        CP16(s + ST_XH + xs0, g_xf + xg0 + k0);
        #pragma unroll
        for (int u = 0; u < 2; u++) {
            const int c  = tid * 2 + u;         // 0..511
            const int r  = c >> 5;              // 0..15 (k row)
            const int cc = c & 31;              // 16B chunk in row
            CP16(s + ST_WH + r * (WPAD * 2) + cc * 16,
                 g_Wh + (size_t)(k0 + r) * D_DIM + n0 + cc * 8);
        }
        CP_COMMIT();
    };

    // warp tile: wm in {0,1} (64 rows), wn in {0..3} (64 cols)
    const int wm = wid & 1;
    const int wn = wid >> 1;

    wmma::fragment<wmma::accumulator, 16, 16, 16, float> acc[4][4];
    #pragma unroll
    for (int i = 0; i < 4; i++)
        #pragma unroll
        for (int j = 0; j < 4; j++) wmma::fill_fragment(acc[i][j], 0.f);

    #pragma unroll
    for (int p = 0; p < 7; p++) issue_stage(p);

    #pragma unroll 2
    for (int kt = 0; kt < KSTEPS; kt++) {
        CP_WAIT(6);
        __syncthreads();
        if (kt + 7 < KSTEPS) issue_stage(kt + 7);
        else                 CP_COMMIT();

        const char* s = smem + (kt & 7) * STAGE_B;
        const __half (*xh)[XPAD] = (const __half(*)[XPAD])(s + ST_XH);
        const __half (*wh)[WPAD] = (const __half(*)[WPAD])(s + ST_WH);

        wmma::fragment<wmma::matrix_a, 16, 16, 16, __half, wmma::row_major> ah[4];
        #pragma unroll
        for (int i = 0; i < 4; i++)
            wmma::load_matrix_sync(ah[i], &xh[wm * 64 + i * 16][0], XPAD);
        #pragma unroll
        for (int j = 0; j < 4; j++) {
            wmma::fragment<wmma::matrix_b, 16, 16, 16, __half, wmma::row_major> bh;
            wmma::load_matrix_sync(bh, &wh[0][wn * 64 + j * 16], WPAD);
            #pragma unroll
            for (int i = 0; i < 4; i++)
                wmma::mma_sync(acc[i][j], ah[i], bh, acc[i][j]);
        }
        __syncthreads();
    }

    // epilogue: acc -> smem (aliases stage slots), reduce against b1/w2
    CP_WAIT(0);
    __syncthreads();
    float (*ep)[EPAD] = (float(*)[EPAD])smem;
    #pragma unroll
    for (int i = 0; i < 4; i++)
        #pragma unroll
        for (int j = 0; j < 4; j++)
            wmma::store_matrix_sync(&ep[wm * 64 + i * 16][wn * 64 + j * 16],
                                    acc[i][j], EPAD, wmma::mem_row_major);
    __syncthreads();

    const int row  = tid >> 1;
    const int half = tid & 1;
    float v = 0.f;
    #pragma unroll 8
    for (int c = 0; c < 128; c++) {
        const int e = half * 128 + c;
        float t = ep[row][e] + s_b1[e];
        t = fmaxf(t, 0.f);
        v = fmaf(t, s_w2[e], v);
    }
    v += __shfl_xor_sync(0xffffffffu, v, 1);
    if (half == 0) g_part[blockIdx.x][(size_t)m0 + row] = v;
}

// ---------------------------------------------------------------------------
// Kernel B: sum partials, 2x2 window softmax + weighted sum over fp16 x.
// (b2 omitted: softmax shift-invariant.)
// ---------------------------------------------------------------------------
__global__ __launch_bounds__(256)
void pool_kernel(float* __restrict__ out)
{
    const int br = blockIdx.x;
    const int b  = br >> 10;
    const int r  = br & 1023;
    const int i  = r >> 5;
    const int j  = r & 31;
    const int t00 = (i * 2) * 64 + (j * 2);
    const int tok[4] = {t00, t00 + 1, t00 + 64, t00 + 65};

    float l[4];
    #pragma unroll
    for (int k = 0; k < 4; k++) {
        const int t = b * N_TOK + tok[k];
        float s = 0.f;
        #pragma unroll
        for (int c = 0; c < NCHUNKS; c++) s += g_part[c][t];
        l[k] = s;
    }
    float mx = fmaxf(fmaxf(l[0], l[1]), fmaxf(l[2], l[3]));
    float e0 = __expf(l[0] - mx), e1 = __expf(l[1] - mx);
    float e2 = __expf(l[2] - mx), e3 = __expf(l[3] - mx);
    float inv = 1.f / (e0 + e1 + e2 + e3);
    const float a[4] = {e0 * inv, e1 * inv, e2 * inv, e3 * inv};

    const size_t xb = (size_t)b * N_TOK * D_DIM;
    const int d = threadIdx.x;               // 4 floats per thread
    float4 ov = {0.f, 0.f, 0.f, 0.f};
    #pragma unroll
    for (int k = 0; k < 4; k++) {
        const __half2* xr = (const __half2*)(g_xf + xb + (size_t)tok[k] * D_DIM);
        float2 p0 = __half22float2(xr[d * 2]);
        float2 p1 = __half22float2(xr[d * 2 + 1]);
        ov.x = fmaf(a[k], p0.x, ov.x);
        ov.y = fmaf(a[k], p0.y, ov.y);
        ov.z = fmaf(a[k], p1.x, ov.z);
        ov.w = fmaf(a[k], p1.y, ov.w);
    }
    ((float4*)(out + (size_t)br * D_DIM))[d] = ov;
}

// ---------------------------------------------------------------------------
extern "C" void kernel_launch(void* const* d_in, const int* in_sizes, int n_in,
                              void* d_out, int out_size)
{
    const float* x  = (const float*)d_in[0];
    const float* W1 = (const float*)d_in[1];
    const float* b1 = (const float*)d_in[2];
    const float* W2 = (const float*)d_in[3];
    float* out = (float*)d_out;

    cudaFuncSetAttribute(logits_wmma_kernel,
                         cudaFuncAttributeMaxDynamicSharedMemorySize, SMEM_TOTAL);

    prep_x_kernel<<<(NTOK_TOTAL * (D_DIM / 4)) / 256, 256>>>(x);
    prep_w_kernel<<<(D_DIM * (D_DIM / 4)) / 256, 256>>>(W1);
    logits_wmma_kernel<<<dim3(NCHUNKS, NTOK_TOTAL / BM), 256, SMEM_TOTAL>>>(b1, W2);
    pool_kernel<<<B_SZ * (N_TOK / 4), 256>>>(out);
}